// round 5
// baseline (speedup 1.0000x reference)
#include <cuda_runtime.h>
#include <math.h>
#include <stdint.h>

#define NB   2
#define L    2048
#define H    8
#define D    64
#define HD   512
#define LHD  1048576
#define P    16
#define C    64
#define NC   32
#define EPSF 1e-6f
#define SD   68      // padded stride for float4 row access
#define SD2  65      // padded stride for scalar row+col access

// ---------------- scratch ----------------
__device__ float g_sq[P*L*D];
__device__ float g_sk[P*L*D];
__device__ float g_vs[P*L*D];
__device__ float g_ST[P*NC*C*C];   // ST[j*64+l] = S[l][j] = q_l . k_j
__device__ float g_ksum[P*NC*D];
__device__ float g_qsum[P*NC*D];
__device__ float g_kso[P*NC*D];
__device__ float g_qsi[P*NC*D];
__device__ float g_si[P*L];
__device__ float g_so[P*L];
__device__ float g_rk[P*L];
__device__ float g_rq[P*L];
__device__ float g_sa[P*L];
__device__ float g_es[P*L];
__device__ float g_essum[P*NC];
__device__ float g_kvc[P*NC*D*D];

typedef unsigned long long ull;
__device__ __forceinline__ ull pack2(float a, float b){
  ull r; asm("mov.b64 %0, {%1,%2};" : "=l"(r) : "f"(a), "f"(b)); return r;
}
__device__ __forceinline__ void fma2(ull &acc, ull a, ull b){
  asm("fma.rn.f32x2 %0, %1, %2, %0;" : "+l"(acc) : "l"(a), "l"(b));
}
__device__ __forceinline__ float2 unpack2(ull v){
  float2 r; asm("mov.b64 {%0,%1}, %2;" : "=f"(r.x), "=f"(r.y) : "l"(v)); return r;
}
__device__ __forceinline__ float sigmoidf_(float x){ return 1.f/(1.f+__expf(-x)); }

// ---------------- K1: sigmoid + chunk sums (256 thr) ----------------
__global__ void __launch_bounds__(256) k_prep(const float* __restrict__ Q, const float* __restrict__ K){
  __shared__ float2 ps[256];
  int c = blockIdx.x, p = blockIdx.y;
  int t = threadIdx.x, d = t&63, g = t>>6;
  const float* Qp = Q + (size_t)(p>>3)*LHD + (size_t)(p&7)*D + d;
  const float* Kp = K + (size_t)(p>>3)*LHD + (size_t)(p&7)*D + d;
  int l0 = c*C;
  int ob = (p*L + l0)*D + d;
  float ks=0.f, qs=0.f;
  #pragma unroll 4
  for(int j=g; j<C; j+=4){
    float qv = sigmoidf_(Qp[(size_t)(l0+j)*HD]);
    float kv = sigmoidf_(Kp[(size_t)(l0+j)*HD]);
    g_sq[ob + j*D] = qv;
    g_sk[ob + j*D] = kv;
    qs += qv; ks += kv;
  }
  ps[t] = make_float2(ks, qs);
  __syncthreads();
  if(t < 64){
    float2 a=ps[t], b=ps[t+64], cc=ps[t+128], dd=ps[t+192];
    g_ksum[(p*NC+c)*D+t] = a.x+b.x+cc.x+dd.x;
    g_qsum[(p*NC+c)*D+t] = a.y+b.y+cc.y+dd.y;
  }
}

// ---------------- K2: gram + si/so (256 thr) ----------------
__global__ void __launch_bounds__(256) k_siso(){
  extern __shared__ float sm[];
  float* sqs = sm;                 // 64*SD
  float* sks = sm + C*SD;          // 64*SD
  float* Ssm = sm + 2*C*SD;        // 64*SD2 : Ssm[j*SD2+l] = S[l][j]
  __shared__ float rsk[C], rsq[C], b1s[C], b2s[C], sis[C], sos[C], kpre[D], qpre[D];
  __shared__ float4 ps4[256];
  __shared__ float2 ps2[256];
  int c=blockIdx.x, p=blockIdx.y, t=threadIdx.x, l=t&63, g=t>>6;
  int j0 = 16*g;
  int base = (p*L + c*C)*D;
  for(int e=t; e<C*D; e+=256){
    sqs[(e>>6)*SD+(e&63)] = g_sq[base+e];
    sks[(e>>6)*SD+(e&63)] = g_sk[base+e];
  }
  { float a=0.f, b=0.f;
    for(int cp=g; cp<c; cp+=4){
      a += g_ksum[(p*NC+cp)*D + l];
      b += g_qsum[(p*NC+cp)*D + l];
    }
    ps2[t] = make_float2(a,b);
  }
  __syncthreads();
  if(t<64){
    kpre[t] = ps2[t].x+ps2[t+64].x+ps2[t+128].x+ps2[t+192].x;
    qpre[t] = ps2[t].y+ps2[t+64].y+ps2[t+128].y+ps2[t+192].y;
  }
  __syncthreads();

  // partial rk/rq/b1/b2 over d range [j0, j0+16)
  float prk=0.f, prq=0.f, pb1=0.f, pb2=0.f;
  for(int dd=j0; dd<j0+16; dd+=4){
    float4 q4 = *(const float4*)(sqs + l*SD + dd);
    float4 k4 = *(const float4*)(sks + l*SD + dd);
    prq += q4.x+q4.y+q4.z+q4.w;
    prk += k4.x+k4.y+k4.z+k4.w;
    pb1 += (q4.x+EPSF)*(kpre[dd]+EPSF) + (q4.y+EPSF)*(kpre[dd+1]+EPSF)
         + (q4.z+EPSF)*(kpre[dd+2]+EPSF) + (q4.w+EPSF)*(kpre[dd+3]+EPSF);
    pb2 += (k4.x+EPSF)*(qpre[dd]+EPSF) + (k4.y+EPSF)*(qpre[dd+1]+EPSF)
         + (k4.z+EPSF)*(qpre[dd+2]+EPSF) + (k4.w+EPSF)*(qpre[dd+3]+EPSF);
  }
  ps4[t] = make_float4(prk,prq,pb1,pb2);

  // gram strip: acc[jj] = q_l . k_{j0+jj}
  float acc[16];
  #pragma unroll
  for(int jj=0;jj<16;jj++) acc[jj]=0.f;
  for(int dd=0; dd<D; dd+=4){
    float4 q4 = *(const float4*)(sqs + l*SD + dd);
    #pragma unroll
    for(int jj=0;jj<16;jj++){
      float4 k4 = *(const float4*)(sks + (j0+jj)*SD + dd);
      acc[jj] = fmaf(q4.x,k4.x, fmaf(q4.y,k4.y, fmaf(q4.z,k4.z, fmaf(q4.w,k4.w, acc[jj]))));
    }
  }
  #pragma unroll
  for(int jj=0;jj<16;jj++) Ssm[(j0+jj)*SD2 + l] = acc[jj];
  __syncthreads();
  if(t<64){
    float4 a=ps4[t], b=ps4[t+64], cc=ps4[t+128], d4=ps4[t+192];
    rsk[t]=a.x+b.x+cc.x+d4.x;  rsq[t]=a.y+b.y+cc.y+d4.y;
    b1s[t]=a.z+b.z+cc.z+d4.z;  b2s[t]=a.w+b.w+cc.w+d4.w;
  }
  __syncthreads();

  // causal partials over i in [j0, j0+16)
  { float p1=0.f, p2=0.f;
    #pragma unroll
    for(int jj=0;jj<16;jj++){
      int i = j0+jj;
      if(i<=l){
        p1 += acc[jj]       + EPSF*rsk[i];
        p2 += Ssm[l*SD2+i]  + EPSF*rsq[i];
      }
    }
    ps2[t] = make_float2(p1,p2);
  }
  __syncthreads();
  if(t<64){
    float dot1 = b1s[t] + ps2[t].x+ps2[t+64].x+ps2[t+128].x+ps2[t+192].x;
    float dot2 = b2s[t] + ps2[t].y+ps2[t+64].y+ps2[t+128].y+ps2[t+192].y;
    float nrm = (float)(c*C + t + 1);
    float si = nrm/dot1, so = nrm/dot2;
    sis[t]=si; sos[t]=so;
    int gl = p*L + c*C + t;
    g_si[gl]=si; g_so[gl]=so; g_rk[gl]=rsk[t]; g_rq[gl]=rsq[t];
  }
  __syncthreads();
  // chunk sums of sk*so, sq*si (thread = (d=l, g over j strip))
  { float a1=0.f, a2=0.f;
    #pragma unroll
    for(int jj=0;jj<16;jj++){
      int j = j0+jj;
      a1 += sks[j*SD+l]*sos[j];
      a2 += sqs[j*SD+l]*sis[j];
    }
    ps2[t] = make_float2(a1,a2);
  }
  __syncthreads();
  if(t<64){
    g_kso[(p*NC+c)*D+t] = ps2[t].x+ps2[t+64].x+ps2[t+128].x+ps2[t+192].x;
    g_qsi[(p*NC+c)*D+t] = ps2[t].y+ps2[t+64].y+ps2[t+128].y+ps2[t+192].y;
  }
  int stbase = (p*NC+c)*C*C;
  for(int e=t; e<C*C; e+=256) g_ST[stbase+e] = Ssm[(e>>6)*SD2 + (e&63)];
}

// ---------------- K3: conserved (256 thr, reloads S) ----------------
__global__ void __launch_bounds__(256) k_conserved(){
  extern __shared__ float sm[];
  float* sqs = sm;                 // 64*SD
  float* sks = sm + C*SD;          // 64*SD
  float* STs = sm + 2*C*SD;        // 64*SD2
  __shared__ float rskv[C], rsqv[C], sis[C], sos[C], kpre[D], qpre[D], facs[C], essh[C];
  __shared__ float2 ps2[256];
  int c=blockIdx.x, p=blockIdx.y, t=threadIdx.x, l=t&63, g=t>>6;
  int j0 = 16*g;
  int base = (p*L + c*C)*D;
  int stbase = (p*NC+c)*C*C;
  for(int e=t; e<C*D; e+=256){
    int r=e>>6, col=e&63;
    sqs[r*SD+col] = g_sq[base+e];
    sks[r*SD+col] = g_sk[base+e];
    STs[r*SD2+col] = g_ST[stbase+e];
  }
  if(t<64){
    int gl = p*L + c*C + t;
    rskv[t]=g_rk[gl]; rsqv[t]=g_rq[gl]; sis[t]=g_si[gl]; sos[t]=g_so[gl];
  }
  { float a=0.f, b=0.f;
    for(int cp=g; cp<c; cp+=4){
      a += g_kso[(p*NC+cp)*D + l];
      b += g_qsi[(p*NC+cp)*D + l];
    }
    ps2[t] = make_float2(a,b);
  }
  __syncthreads();
  if(t<64){
    kpre[t] = ps2[t].x+ps2[t+64].x+ps2[t+128].x+ps2[t+192].x;
    qpre[t] = ps2[t].y+ps2[t+64].y+ps2[t+128].y+ps2[t+192].y;
  }
  __syncthreads();

  // combined partial: prefix-base over d strip + causal over i strip
  float p3=0.f, p4=0.f;
  for(int dd=j0; dd<j0+16; dd+=4){
    float4 q4 = *(const float4*)(sqs + l*SD + dd);
    float4 k4 = *(const float4*)(sks + l*SD + dd);
    p3 += (q4.x+EPSF)*(kpre[dd]+EPSF) + (q4.y+EPSF)*(kpre[dd+1]+EPSF)
        + (q4.z+EPSF)*(kpre[dd+2]+EPSF) + (q4.w+EPSF)*(kpre[dd+3]+EPSF);
    p4 += (k4.x+EPSF)*(qpre[dd]+EPSF) + (k4.y+EPSF)*(qpre[dd+1]+EPSF)
        + (k4.z+EPSF)*(qpre[dd+2]+EPSF) + (k4.w+EPSF)*(qpre[dd+3]+EPSF);
  }
  #pragma unroll
  for(int jj=0;jj<16;jj++){
    int i = j0+jj;
    if(i<=l){
      p3 += sos[i]*(STs[i*SD2+l] + EPSF*rskv[i]);
      p4 += sis[i]*(STs[l*SD2+i] + EPSF*rsqv[i]);
    }
  }
  ps2[t] = make_float2(p3,p4);
  __syncthreads();
  if(t<64){
    float dot3 = ps2[t].x+ps2[t+64].x+ps2[t+128].x+ps2[t+192].x;
    float dot4 = ps2[t].y+ps2[t+64].y+ps2[t+128].y+ps2[t+192].y;
    float nrm = (float)(c*C + t + 1);
    float sa  = sigmoidf_(dot3/nrm);
    float cso = dot4/nrm; cso = fminf(1.f, fmaxf(-1.f, cso));
    float es  = __expf(cso);
    int gl = p*L + c*C + t;
    g_sa[gl]=sa; g_es[gl]=es;
    essh[t]=es; facs[t]=sis[t]/nrm;
  }
  __syncthreads();
  for(int e=t; e<C*D; e+=256)
    g_sq[base+e] = sqs[(e>>6)*SD+(e&63)] * facs[e>>6];
  if(t<32){
    float v = essh[t] + essh[t+32];
    #pragma unroll
    for(int o=16;o;o>>=1) v += __shfl_down_sync(0xffffffffu, v, o);
    if(t==0) g_essum[p*NC+c] = v;
  }
}

// ---------------- K4: v_scaled + chunk KV (256 thr, parallel scan) ----------------
__global__ void __launch_bounds__(256) k_vkv(const float* __restrict__ V){
  extern __shared__ float sm[];
  float* sks = sm;             // 4096
  float* vss = sm + C*D;       // 4096
  float* kst = sm + 2*C*D;     // 64*SD
  __shared__ float ess[C], comp[C];
  __shared__ float prefsh, wtot0;
  int c=blockIdx.x, p=blockIdx.y, t=threadIdx.x, d=t&63, g=t>>6;
  int m0 = 16*g;
  int base = (p*L + c*C)*D;
  for(int e=t; e<C*D; e+=256) sks[e] = g_sk[base+e];
  if(t<64) ess[t] = g_es[p*L + c*C + t];
  if(t<32){
    float v = (t < c) ? g_essum[p*NC + t] : 0.f;
    #pragma unroll
    for(int o=16;o;o>>=1) v += __shfl_down_sync(0xffffffffu, v, o);
    if(t==0) prefsh = v;
  }
  __syncthreads();
  // 2-warp inclusive scan of ess
  float xscan = 0.f;
  if(t<64){
    xscan = ess[t];
    #pragma unroll
    for(int o=1;o<32;o<<=1){
      float y = __shfl_up_sync(0xffffffffu, xscan, o);
      if((t&31) >= o) xscan += y;
    }
    if(t==31) wtot0 = xscan;
  }
  __syncthreads();
  if(t<64){
    float cum = prefsh + xscan + ((t>=32)? wtot0 : 0.f);
    comp[t] = ess[t]/cum * (float)(c*C + t + 1);
  }
  __syncthreads();
  const float* Vp = V + (size_t)(p>>3)*LHD + (size_t)(p&7)*D;
  for(int e=t; e<C*D; e+=256){
    int j = e>>6, d2 = e&63;
    float x = Vp[(size_t)(c*C+j)*HD + d2]*comp[j];
    vss[e] = x;
    g_vs[base+e] = x;
  }
  __syncthreads();
  // KV strip: thread (d, m-strip g)
  ull acc2[8];
  #pragma unroll
  for(int m=0;m<8;m++) acc2[m]=0ull;
  for(int j=0;j<C;j++){
    float a = sks[j*D + d];
    ull a2 = pack2(a, a);
    const double2* vr = (const double2*)(vss + j*D + m0);
    #pragma unroll
    for(int m=0;m<4;m++){
      double2 w = vr[m];
      fma2(acc2[2*m],   a2, (ull)__double_as_longlong(w.x));
      fma2(acc2[2*m+1], a2, (ull)__double_as_longlong(w.y));
    }
  }
  #pragma unroll
  for(int m=0;m<4;m++){
    float2 v0 = unpack2(acc2[2*m]);
    float2 v1 = unpack2(acc2[2*m+1]);
    *(float4*)(kst + d*SD + m0 + 4*m) = make_float4(v0.x,v0.y,v1.x,v1.y);
  }
  __syncthreads();
  size_t kb = (size_t)(p*NC+c)*D*D;
  for(int e=t; e<D*D; e+=256) g_kvc[kb+e] = kst[(e>>6)*SD + (e&63)];
}

// ---------------- K5: exclusive scan of chunk KV sums ----------------
__global__ void k_scan_kv(){
  int p = blockIdx.y;
  int e4 = blockIdx.x*256 + threadIdx.x;
  size_t stride = (size_t)D*D;
  size_t base = (size_t)p*NC*stride + (size_t)e4*4;
  float4 run = make_float4(0.f,0.f,0.f,0.f);
  #pragma unroll
  for(int c=0;c<NC;c++){
    float4 v = *(const float4*)(g_kvc + base + c*stride);
    *(float4*)(g_kvc + base + c*stride) = run;
    run.x += v.x; run.y += v.y; run.z += v.z; run.w += v.w;
  }
}

// ---------------- K6: causal output (256 thr) ----------------
__global__ void __launch_bounds__(256) k_out(float* __restrict__ OUT){
  extern __shared__ float sm[];
  float* qss = sm;               // 64*SD (q_scaled; reused as out staging)
  float* STs = sm + C*SD;        // 64*SD2
  float* vss = STs + C*SD2;      // 4096
  float* kvs = vss + C*D;        // 4096
  __shared__ float sa_s[C], fls[C];
  int c=blockIdx.x, p=blockIdx.y, t=threadIdx.x, l=t&63, g=t>>6;
  int m0 = 16*g;
  int base = (p*L + c*C)*D;
  size_t kb = (size_t)(p*NC+c)*D*D;
  int stbase = (p*NC+c)*C*C;
  for(int e=t; e<C*D; e+=256){
    int r=e>>6, col=e&63;
    qss[r*SD + col]  = g_sq[base+e];
    STs[r*SD2 + col] = g_ST[stbase+e];
    vss[e] = g_vs[base+e];
    kvs[e] = g_kvc[kb+e];
  }
  if(t<64){
    int gl = p*L + c*C + t;
    sa_s[t] = g_sa[gl];
    fls[t]  = g_si[gl] / (float)(c*C + t + 1);
  }
  __syncthreads();

  ull o2[8];
  #pragma unroll
  for(int m=0;m<8;m++) o2[m]=0ull;
  float fl = fls[l];

  // intra-chunk causal
  for(int i=0;i<=l;i++){
    float s = fl * STs[i*SD2 + l];
    ull s2 = pack2(s, s);
    const double2* vr = (const double2*)(vss + i*D + m0);
    #pragma unroll
    for(int m=0;m<4;m++){
      double2 w = vr[m];
      fma2(o2[2*m],   s2, (ull)__double_as_longlong(w.x));
      fma2(o2[2*m+1], s2, (ull)__double_as_longlong(w.y));
    }
  }
  // inter-chunk: q_scaled[l] @ KVprefix (m strip)
  for(int dd=0; dd<D; dd+=4){
    float4 q4 = *(const float4*)(qss + l*SD + dd);
    #pragma unroll
    for(int u=0;u<4;u++){
      float qd = (u==0)?q4.x:(u==1)?q4.y:(u==2)?q4.z:q4.w;
      ull q2 = pack2(qd, qd);
      const double2* kr = (const double2*)(kvs + (dd+u)*D + m0);
      #pragma unroll
      for(int m=0;m<4;m++){
        double2 w = kr[m];
        fma2(o2[2*m],   q2, (ull)__double_as_longlong(w.x));
        fma2(o2[2*m+1], q2, (ull)__double_as_longlong(w.y));
      }
    }
  }
  float sa = sa_s[l];
  __syncthreads();   // all qss reads complete before overwrite
  #pragma unroll
  for(int m=0;m<4;m++){
    float2 v0 = unpack2(o2[2*m]);
    float2 v1 = unpack2(o2[2*m+1]);
    *(float4*)(qss + l*SD + m0 + 4*m) = make_float4(v0.x*sa, v0.y*sa, v1.x*sa, v1.y*sa);
  }
  __syncthreads();
  float* op = OUT + (size_t)(p>>3)*LHD + (size_t)(c*C)*HD + (size_t)(p&7)*D;
  for(int e=t; e<C*D; e+=256)
    op[(size_t)(e>>6)*HD + (e&63)] = qss[(e>>6)*SD + (e&63)];
}

// ---------------- launch ----------------
extern "C" void kernel_launch(void* const* d_in, const int* in_sizes, int n_in,
                              void* d_out, int out_size){
  const float* Q = (const float*)d_in[0];
  const float* K = (const float*)d_in[1];
  const float* V = (const float*)d_in[2];
  float* OUT = (float*)d_out;

  const int SM_SISO = (2*C*SD + C*SD2)*sizeof(float);
  const int SM_CONS = (2*C*SD + C*SD2)*sizeof(float);
  const int SM_VKV  = (2*C*D + C*SD)*sizeof(float);
  const int SM_OUT  = (C*SD + C*SD2 + 2*C*D)*sizeof(float);
  cudaFuncSetAttribute(k_siso,      cudaFuncAttributeMaxDynamicSharedMemorySize, SM_SISO);
  cudaFuncSetAttribute(k_conserved, cudaFuncAttributeMaxDynamicSharedMemorySize, SM_CONS);
  cudaFuncSetAttribute(k_vkv,       cudaFuncAttributeMaxDynamicSharedMemorySize, SM_VKV);
  cudaFuncSetAttribute(k_out,       cudaFuncAttributeMaxDynamicSharedMemorySize, SM_OUT);

  dim3 gpc(NC, P);
  k_prep<<<gpc, 256>>>(Q, K);
  k_siso<<<gpc, 256, SM_SISO>>>();
  k_conserved<<<gpc, 256, SM_CONS>>>();
  k_vkv<<<gpc, 256, SM_VKV>>>(V);
  k_scan_kv<<<dim3(4, P), 256>>>();
  k_out<<<gpc, 256, SM_OUT>>>(OUT);
}

// round 6
// speedup vs baseline: 1.7390x; 1.7390x over previous
#include <cuda_runtime.h>
#include <math.h>
#include <stdint.h>

#define NB   2
#define L    2048
#define H    8
#define D    64
#define HD   512
#define LHD  1048576
#define P    16
#define C    64
#define NC   32
#define EPSF 1e-6f
#define SD   68      // padded stride (floats), 16B-aligned rows

// ---------------- scratch ----------------
__device__ float g_sq[P*L*D];      // sigmoid(q); overwritten with q_scaled
__device__ float g_sk[P*L*D];
__device__ float g_vs[P*L*D];
__device__ float g_ST[P*NC*C*C];   // g_ST[j*64+l] = S[l][j]
__device__ float g_ksum[P*NC*D];
__device__ float g_qsum[P*NC*D];
__device__ float g_kso[P*NC*D];
__device__ float g_qsi[P*NC*D];
__device__ float g_si[P*L];
__device__ float g_so[P*L];
__device__ float g_rk[P*L];
__device__ float g_rq[P*L];
__device__ float g_sa[P*L];
__device__ float g_es[P*L];
__device__ float g_essum[P*NC];
__device__ float g_kvc[P*NC*D*D];

typedef unsigned long long ull;
__device__ __forceinline__ ull pack2(float a, float b){
  ull r; asm("mov.b64 %0, {%1,%2};" : "=l"(r) : "f"(a), "f"(b)); return r;
}
__device__ __forceinline__ void fma2(ull &acc, ull a, ull b){
  asm("fma.rn.f32x2 %0, %1, %2, %0;" : "+l"(acc) : "l"(a), "l"(b));
}
__device__ __forceinline__ ull mul2(ull a, ull b){
  ull r; asm("mul.rn.f32x2 %0, %1, %2;" : "=l"(r) : "l"(a), "l"(b)); return r;
}
__device__ __forceinline__ float2 unpack2(ull v){
  float2 r; asm("mov.b64 {%0,%1}, %2;" : "=f"(r.x), "=f"(r.y) : "l"(v)); return r;
}
__device__ __forceinline__ float sigmoidf_(float x){ return 1.f/(1.f+__expf(-x)); }
__device__ __forceinline__ float f4get(const float4& v, int u){
  return (u==0)?v.x:(u==1)?v.y:(u==2)?v.z:v.w;
}

// ---------------- K1: sigmoid + chunk sums (256 thr) ----------------
__global__ void __launch_bounds__(256) k_prep(const float* __restrict__ Q, const float* __restrict__ K){
  __shared__ float2 ps[256];
  int c = blockIdx.x, p = blockIdx.y;
  int t = threadIdx.x, d = t&63, g = t>>6;
  const float* Qp = Q + (size_t)(p>>3)*LHD + (size_t)(p&7)*D + d;
  const float* Kp = K + (size_t)(p>>3)*LHD + (size_t)(p&7)*D + d;
  int l0 = c*C;
  int ob = (p*L + l0)*D + d;
  float ks=0.f, qs=0.f;
  #pragma unroll 4
  for(int j=g; j<C; j+=4){
    float qv = sigmoidf_(Qp[(size_t)(l0+j)*HD]);
    float kv = sigmoidf_(Kp[(size_t)(l0+j)*HD]);
    g_sq[ob + j*D] = qv;
    g_sk[ob + j*D] = kv;
    qs += qv; ks += kv;
  }
  ps[t] = make_float2(ks, qs);
  __syncthreads();
  if(t < 64){
    float2 a=ps[t], b=ps[t+64], cc=ps[t+128], dd=ps[t+192];
    g_ksum[(p*NC+c)*D+t] = a.x+b.x+cc.x+dd.x;
    g_qsum[(p*NC+c)*D+t] = a.y+b.y+cc.y+dd.y;
  }
}

// ---------------- K2: gram + si/so (128 thr, 4x8 reg tiles) ----------------
__global__ void __launch_bounds__(128) k_siso(){
  extern __shared__ float sm[];
  float* sqs = sm;            // [l][d] stride SD
  float* skT = sm + C*SD;     // [d][j] stride SD (transposed k)
  float* Ssm = sm + 2*C*SD;   // [l][j] stride SD
  __shared__ float rsk[C], rsq[C], kpre[D], qpre[D], b1s[C], b2s[C], sis[C], sos[C];
  int c=blockIdx.x, p=blockIdx.y, t=threadIdx.x;
  int base = (p*L + c*C)*D;
  const float4* gq = (const float4*)(g_sq+base);
  const float4* gk = (const float4*)(g_sk+base);
  for(int i=t;i<1024;i+=128){
    int row = i>>4, col4 = (i&15)*4;
    float4 q4 = gq[i];
    *(float4*)(sqs + row*SD + col4) = q4;
    float4 k4 = gk[i];
    skT[(col4  )*SD + row] = k4.x;
    skT[(col4+1)*SD + row] = k4.y;
    skT[(col4+2)*SD + row] = k4.z;
    skT[(col4+3)*SD + row] = k4.w;
  }
  if(t<64){
    float a=0.f; for(int cp=0;cp<c;cp++) a += g_ksum[(p*NC+cp)*D+t];
    kpre[t]=a;
  } else {
    int d=t-64; float a=0.f; for(int cp=0;cp<c;cp++) a += g_qsum[(p*NC+cp)*D+d];
    qpre[d]=a;
  }
  __syncthreads();

  // scalar per-l dots (split halves)
  if(t<64){
    int l=t; float rq=0.f, b1=0.f;
    for(int dd=0;dd<D;dd+=4){
      float4 q4 = *(const float4*)(sqs + l*SD + dd);
      rq += q4.x+q4.y+q4.z+q4.w;
      b1 += (q4.x+EPSF)*(kpre[dd]+EPSF) + (q4.y+EPSF)*(kpre[dd+1]+EPSF)
          + (q4.z+EPSF)*(kpre[dd+2]+EPSF) + (q4.w+EPSF)*(kpre[dd+3]+EPSF);
    }
    rsq[l]=rq; b1s[l]=b1;
  } else {
    int l=t-64; float rk=0.f, b2=0.f;
    for(int d=0;d<D;d++){
      float kv = skT[d*SD + l];
      rk += kv; b2 += (kv+EPSF)*(qpre[d]+EPSF);
    }
    rsk[l]=rk; b2s[l]=b2;
  }

  // gram: S[l][j], thread tile 4l x 8j, FMA2 packed along j
  int lg=t>>3, mg=t&7, l0=4*lg, j0=8*mg;
  ull acc[16];
  #pragma unroll
  for(int m=0;m<16;m++) acc[m]=0ull;
  for(int dq=0; dq<D; dq+=4){
    float4 q4[4];
    #pragma unroll
    for(int ll=0;ll<4;ll++) q4[ll] = *(const float4*)(sqs + (l0+ll)*SD + dq);
    #pragma unroll
    for(int du=0;du<4;du++){
      const double2* kr = (const double2*)(skT + (dq+du)*SD + j0);
      double2 ka = kr[0], kb = kr[1];
      ull k0=(ull)__double_as_longlong(ka.x), k1=(ull)__double_as_longlong(ka.y);
      ull k2=(ull)__double_as_longlong(kb.x), k3=(ull)__double_as_longlong(kb.y);
      #pragma unroll
      for(int ll=0;ll<4;ll++){
        float qv = f4get(q4[ll], du);
        ull q2 = pack2(qv,qv);
        fma2(acc[ll*4+0], q2, k0);
        fma2(acc[ll*4+1], q2, k1);
        fma2(acc[ll*4+2], q2, k2);
        fma2(acc[ll*4+3], q2, k3);
      }
    }
  }
  #pragma unroll
  for(int ll=0;ll<4;ll++){
    float2 a0=unpack2(acc[ll*4+0]), a1=unpack2(acc[ll*4+1]);
    float2 a2=unpack2(acc[ll*4+2]), a3=unpack2(acc[ll*4+3]);
    *(float4*)(Ssm + (l0+ll)*SD + j0)     = make_float4(a0.x,a0.y,a1.x,a1.y);
    *(float4*)(Ssm + (l0+ll)*SD + j0 + 4) = make_float4(a2.x,a2.y,a3.x,a3.y);
  }
  __syncthreads();

  // causal sums
  if(t<64){
    int l=t; float dot1=b1s[l];
    for(int i=0;i<=l;i++) dot1 += Ssm[l*SD+i] + EPSF*rsk[i];
    float nrm = (float)(c*C + l + 1);
    float si = nrm/dot1;
    sis[l]=si;
    int gl = p*L + c*C + l;
    g_si[gl]=si; g_rq[gl]=rsq[l];
  } else {
    int l=t-64; float dot2=b2s[l];
    for(int i=0;i<=l;i++) dot2 += Ssm[i*SD+l] + EPSF*rsq[i];
    float nrm = (float)(c*C + l + 1);
    float so = nrm/dot2;
    sos[l]=so;
    int gl = p*L + c*C + l;
    g_so[gl]=so; g_rk[gl]=rsk[l];
  }
  __syncthreads();

  // chunk sums of sk*so / sq*si
  if(t<64){
    int d=t; float a1=0.f;
    for(int j=0;j<C;j++) a1 += skT[d*SD+j]*sos[j];
    g_kso[(p*NC+c)*D+d] = a1;
  } else {
    int d=t-64; float a2=0.f;
    for(int j=0;j<C;j++) a2 += sqs[j*SD+d]*sis[j];
    g_qsi[(p*NC+c)*D+d] = a2;
  }
  // store S to global: g_ST[j*64+l] = S[l][j] (coalesced, conflict-free)
  int stbase = (p*NC+c)*C*C;
  for(int e4=t; e4<1024; e4+=128){
    int l0w = (e4*4)&63, j = e4>>4;
    float4 v = make_float4(Ssm[(l0w  )*SD+j], Ssm[(l0w+1)*SD+j],
                           Ssm[(l0w+2)*SD+j], Ssm[(l0w+3)*SD+j]);
    *(float4*)(g_ST + stbase + e4*4) = v;
  }
}

// ---------------- K3: conserved (128 thr) ----------------
__global__ void __launch_bounds__(128) k_conserved(){
  extern __shared__ float sm[];
  float* sqs = sm;            // [l][d] stride SD
  float* sks = sm + C*SD;     // [l][d] stride SD
  float* STs = sm + 2*C*SD;   // [j][l] stride SD (S[l][j] at STs[j*SD+l])
  __shared__ float rskv[C], rsqv[C], sis[C], sos[C], kpre[D], qpre[D], facs[C], essh[C];
  int c=blockIdx.x, p=blockIdx.y, t=threadIdx.x;
  int base = (p*L + c*C)*D;
  int stbase = (p*NC+c)*C*C;
  const float4* gq = (const float4*)(g_sq+base);
  const float4* gk = (const float4*)(g_sk+base);
  const float4* gs = (const float4*)(g_ST+stbase);
  for(int i=t;i<1024;i+=128){
    int row = i>>4, col4 = (i&15)*4;
    *(float4*)(sqs + row*SD + col4) = gq[i];
    *(float4*)(sks + row*SD + col4) = gk[i];
    *(float4*)(STs + row*SD + col4) = gs[i];
  }
  if(t<64){
    int gl = p*L + c*C + t;
    rskv[t]=g_rk[gl]; sos[t]=g_so[gl];
    float a=0.f; for(int cp=0;cp<c;cp++) a += g_kso[(p*NC+cp)*D+t];
    kpre[t]=a;
  } else {
    int l=t-64; int gl = p*L + c*C + l;
    rsqv[l]=g_rq[gl]; sis[l]=g_si[gl];
    float a=0.f; for(int cp=0;cp<c;cp++) a += g_qsi[(p*NC+cp)*D+l];
    qpre[l]=a;
  }
  __syncthreads();

  if(t<64){
    int l=t; float b3=0.f;
    for(int dd=0;dd<D;dd+=4){
      float4 q4 = *(const float4*)(sqs + l*SD + dd);
      b3 += (q4.x+EPSF)*(kpre[dd]+EPSF) + (q4.y+EPSF)*(kpre[dd+1]+EPSF)
          + (q4.z+EPSF)*(kpre[dd+2]+EPSF) + (q4.w+EPSF)*(kpre[dd+3]+EPSF);
    }
    for(int i=0;i<=l;i++) b3 += sos[i]*(STs[i*SD+l] + EPSF*rskv[i]);
    float nrm = (float)(c*C + l + 1);
    float sa = sigmoidf_(b3/nrm);
    g_sa[p*L + c*C + l] = sa;
  } else {
    int l=t-64; float b4=0.f;
    for(int dd=0;dd<D;dd+=4){
      float4 k4 = *(const float4*)(sks + l*SD + dd);
      b4 += (k4.x+EPSF)*(qpre[dd]+EPSF) + (k4.y+EPSF)*(qpre[dd+1]+EPSF)
          + (k4.z+EPSF)*(qpre[dd+2]+EPSF) + (k4.w+EPSF)*(qpre[dd+3]+EPSF);
    }
    for(int i=0;i<=l;i++) b4 += sis[i]*(STs[l*SD+i] + EPSF*rsqv[i]);
    float nrm = (float)(c*C + l + 1);
    float cso = b4/nrm; cso = fminf(1.f, fmaxf(-1.f, cso));
    float es = __expf(cso);
    g_es[p*L + c*C + l] = es;
    essh[l]=es;
    facs[l]=sis[l]/nrm;
  }
  __syncthreads();
  // q_scaled overwrite
  float4* gqo = (float4*)(g_sq+base);
  for(int i=t;i<1024;i+=128){
    int row = i>>4, col4 = (i&15)*4;
    float4 v = *(const float4*)(sqs + row*SD + col4);
    float f = facs[row];
    gqo[i] = make_float4(v.x*f, v.y*f, v.z*f, v.w*f);
  }
  if(t<32){
    float v = essh[t] + essh[t+32];
    #pragma unroll
    for(int o=16;o;o>>=1) v += __shfl_down_sync(0xffffffffu, v, o);
    if(t==0) g_essum[p*NC+c] = v;
  }
}

// ---------------- K4: v_scaled + chunk KV (128 thr, 4x8 tiles) ----------------
__global__ void __launch_bounds__(128) k_vkv(const float* __restrict__ V){
  __shared__ __align__(16) float sks[C*D];
  __shared__ __align__(16) float vss[C*D];
  __shared__ float ess[C], comp[C];
  __shared__ float prefsh, wtot0;
  int c=blockIdx.x, p=blockIdx.y, t=threadIdx.x;
  int base = (p*L + c*C)*D;
  const float4* gk = (const float4*)(g_sk+base);
  for(int i=t;i<1024;i+=128) ((float4*)sks)[i] = gk[i];
  if(t<64) ess[t] = g_es[p*L + c*C + t];
  if(t<32){
    float v = (t < c) ? g_essum[p*NC + t] : 0.f;
    #pragma unroll
    for(int o=16;o;o>>=1) v += __shfl_down_sync(0xffffffffu, v, o);
    if(t==0) prefsh = v;
  }
  __syncthreads();
  float xscan = 0.f;
  if(t<64){
    xscan = ess[t];
    #pragma unroll
    for(int o=1;o<32;o<<=1){
      float y = __shfl_up_sync(0xffffffffu, xscan, o);
      if((t&31) >= o) xscan += y;
    }
    if(t==31) wtot0 = xscan;
  }
  __syncthreads();
  if(t<64){
    float cum = prefsh + xscan + ((t>=32)? wtot0 : 0.f);
    comp[t] = ess[t]/cum * (float)(c*C + t + 1);
  }
  __syncthreads();
  const float* Vp = V + (size_t)(p>>3)*LHD + (size_t)(p&7)*D;
  float4* gvs = (float4*)(g_vs+base);
  for(int i=t;i<1024;i+=128){
    int j = i>>4, col4 = (i&15)*4;
    float4 v = *(const float4*)(Vp + (size_t)(c*C+j)*HD + col4);
    float f = comp[j];
    float4 x = make_float4(v.x*f, v.y*f, v.z*f, v.w*f);
    ((float4*)vss)[i] = x;
    gvs[i] = x;
  }
  __syncthreads();
  // KV[d][m] += sk[j][d]*vs[j][m], tile 4d x 8m
  int dg=t>>3, mg=t&7, d0=4*dg, m0=8*mg;
  ull acc[16];
  #pragma unroll
  for(int m=0;m<16;m++) acc[m]=0ull;
  #pragma unroll 4
  for(int j=0;j<C;j++){
    float4 sk4 = *(const float4*)(sks + j*D + d0);
    const double2* vr = (const double2*)(vss + j*D + m0);
    double2 va = vr[0], vb = vr[1];
    ull v0=(ull)__double_as_longlong(va.x), v1=(ull)__double_as_longlong(va.y);
    ull v2=(ull)__double_as_longlong(vb.x), v3=(ull)__double_as_longlong(vb.y);
    #pragma unroll
    for(int dd=0;dd<4;dd++){
      float a = f4get(sk4, dd);
      ull a2 = pack2(a,a);
      fma2(acc[dd*4+0], a2, v0);
      fma2(acc[dd*4+1], a2, v1);
      fma2(acc[dd*4+2], a2, v2);
      fma2(acc[dd*4+3], a2, v3);
    }
  }
  size_t kb = (size_t)(p*NC+c)*D*D;
  #pragma unroll
  for(int dd=0;dd<4;dd++){
    float2 a0=unpack2(acc[dd*4+0]), a1=unpack2(acc[dd*4+1]);
    float2 a2=unpack2(acc[dd*4+2]), a3=unpack2(acc[dd*4+3]);
    *(float4*)(g_kvc + kb + (d0+dd)*D + m0)     = make_float4(a0.x,a0.y,a1.x,a1.y);
    *(float4*)(g_kvc + kb + (d0+dd)*D + m0 + 4) = make_float4(a2.x,a2.y,a3.x,a3.y);
  }
}

// ---------------- K5: exclusive scan of chunk KV sums ----------------
__global__ void k_scan_kv(){
  int p = blockIdx.y;
  int e4 = blockIdx.x*256 + threadIdx.x;
  size_t stride = (size_t)D*D;
  size_t base = (size_t)p*NC*stride + (size_t)e4*4;
  float4 run = make_float4(0.f,0.f,0.f,0.f);
  #pragma unroll
  for(int c=0;c<NC;c++){
    float4 v = *(const float4*)(g_kvc + base + c*stride);
    *(float4*)(g_kvc + base + c*stride) = run;
    run.x += v.x; run.y += v.y; run.z += v.z; run.w += v.w;
  }
}

// ---------------- K6: causal output (128 thr, 4x8 tiles) ----------------
__global__ void __launch_bounds__(128) k_out(float* __restrict__ OUT){
  extern __shared__ float sm[];
  float* qss = sm;             // [l][d] stride SD (q_scaled)
  float* STs = sm + C*SD;      // [i][l] stride SD (S[l][i] at STs[i*SD+l])
  float* vss = sm + 2*C*SD;          // [i][m] stride 64
  float* kvs = sm + 2*C*SD + C*D;    // [d][m] stride 64
  __shared__ float sa_s[C], fls[C];
  int c=blockIdx.x, p=blockIdx.y, t=threadIdx.x;
  int base = (p*L + c*C)*D;
  size_t kb = (size_t)(p*NC+c)*D*D;
  int stbase = (p*NC+c)*C*C;
  const float4* gq = (const float4*)(g_sq+base);
  const float4* gs = (const float4*)(g_ST+stbase);
  const float4* gv = (const float4*)(g_vs+base);
  const float4* gkv = (const float4*)(g_kvc+kb);
  for(int i=t;i<1024;i+=128){
    int row = i>>4, col4 = (i&15)*4;
    *(float4*)(qss + row*SD + col4) = gq[i];
    *(float4*)(STs + row*SD + col4) = gs[i];
    ((float4*)vss)[i] = gv[i];
    ((float4*)kvs)[i] = gkv[i];
  }
  if(t<64){
    int gl = p*L + c*C + t;
    sa_s[t] = g_sa[gl];
    fls[t]  = g_si[gl] / (float)(c*C + t + 1);
  }
  __syncthreads();

  int lg=t>>3, mg=t&7, l0=4*lg, m0=8*mg;
  ull acc[16];
  #pragma unroll
  for(int m=0;m<16;m++) acc[m]=0ull;

  // intra-chunk: acc[ll][m] += S[l][i]*vs[i][m], i <= l (per-thread bound)
  for(int i=0;i<=l0+3;i++){
    float4 st4 = *(const float4*)(STs + i*SD + l0);
    const double2* vr = (const double2*)(vss + i*D + m0);
    double2 va = vr[0], vb = vr[1];
    ull v0=(ull)__double_as_longlong(va.x), v1=(ull)__double_as_longlong(va.y);
    ull v2=(ull)__double_as_longlong(vb.x), v3=(ull)__double_as_longlong(vb.y);
    #pragma unroll
    for(int ll=0;ll<4;ll++){
      float s = (i <= l0+ll) ? f4get(st4, ll) : 0.f;
      ull s2 = pack2(s,s);
      fma2(acc[ll*4+0], s2, v0);
      fma2(acc[ll*4+1], s2, v1);
      fma2(acc[ll*4+2], s2, v2);
      fma2(acc[ll*4+3], s2, v3);
    }
  }
  // scale intra by fl[l]
  #pragma unroll
  for(int ll=0;ll<4;ll++){
    float f = fls[l0+ll];
    ull f2 = pack2(f,f);
    acc[ll*4+0] = mul2(acc[ll*4+0], f2);
    acc[ll*4+1] = mul2(acc[ll*4+1], f2);
    acc[ll*4+2] = mul2(acc[ll*4+2], f2);
    acc[ll*4+3] = mul2(acc[ll*4+3], f2);
  }
  // inter-chunk: acc[ll][m] += q_scaled[l][d]*KV[d][m]
  for(int dq=0; dq<D; dq+=4){
    float4 q4[4];
    #pragma unroll
    for(int ll=0;ll<4;ll++) q4[ll] = *(const float4*)(qss + (l0+ll)*SD + dq);
    #pragma unroll
    for(int du=0;du<4;du++){
      const double2* kr = (const double2*)(kvs + (dq+du)*D + m0);
      double2 ka = kr[0], kb2 = kr[1];
      ull k0=(ull)__double_as_longlong(ka.x), k1=(ull)__double_as_longlong(ka.y);
      ull k2=(ull)__double_as_longlong(kb2.x), k3=(ull)__double_as_longlong(kb2.y);
      #pragma unroll
      for(int ll=0;ll<4;ll++){
        float qv = f4get(q4[ll], du);
        ull q2 = pack2(qv,qv);
        fma2(acc[ll*4+0], q2, k0);
        fma2(acc[ll*4+1], q2, k1);
        fma2(acc[ll*4+2], q2, k2);
        fma2(acc[ll*4+3], q2, k3);
      }
    }
  }
  // write: out = sa * acc
  float* op = OUT + (size_t)(p>>3)*LHD + (size_t)(c*C)*HD + (size_t)(p&7)*D;
  #pragma unroll
  for(int ll=0;ll<4;ll++){
    float sa = sa_s[l0+ll];
    float2 a0=unpack2(acc[ll*4+0]), a1=unpack2(acc[ll*4+1]);
    float2 a2=unpack2(acc[ll*4+2]), a3=unpack2(acc[ll*4+3]);
    *(float4*)(op + (size_t)(l0+ll)*HD + m0)     = make_float4(a0.x*sa,a0.y*sa,a1.x*sa,a1.y*sa);
    *(float4*)(op + (size_t)(l0+ll)*HD + m0 + 4) = make_float4(a2.x*sa,a2.y*sa,a3.x*sa,a3.y*sa);
  }
}

// ---------------- launch ----------------
extern "C" void kernel_launch(void* const* d_in, const int* in_sizes, int n_in,
                              void* d_out, int out_size){
  const float* Q = (const float*)d_in[0];
  const float* K = (const float*)d_in[1];
  const float* V = (const float*)d_in[2];
  float* OUT = (float*)d_out;

  const int SM_3T = 3*C*SD*sizeof(float);             // 52224
  const int SM_OUT = (2*C*SD + 2*C*D)*sizeof(float);  // 67584
  cudaFuncSetAttribute(k_siso,      cudaFuncAttributeMaxDynamicSharedMemorySize, SM_3T);
  cudaFuncSetAttribute(k_conserved, cudaFuncAttributeMaxDynamicSharedMemorySize, SM_3T);
  cudaFuncSetAttribute(k_out,       cudaFuncAttributeMaxDynamicSharedMemorySize, SM_OUT);

  dim3 gpc(NC, P);
  k_prep<<<gpc, 256>>>(Q, K);
  k_siso<<<gpc, 128, SM_3T>>>();
  k_conserved<<<gpc, 128, SM_3T>>>();
  k_vkv<<<gpc, 128>>>(V);
  k_scan_kv<<<dim3(4, P), 256>>>();
  k_out<<<gpc, 128, SM_OUT>>>(OUT);
}

// round 8
// speedup vs baseline: 2.0301x; 1.1674x over previous
#include <cuda_runtime.h>
#include <math.h>
#include <stdint.h>

#define NB   2
#define L    2048
#define H    8
#define D    64
#define HD   512
#define LHD  1048576
#define P    16
#define C    64
#define NC   32
#define EPSF 1e-6f
#define SDT  68      // padded stride for transposed-k tile
#define SDS  68      // padded stride for S tile in k_siso/k_conserved

// ---------------- scratch ----------------
__device__ float g_sq[P*L*D];      // sigmoid(q); overwritten with q_scaled
__device__ float g_sk[P*L*D];
__device__ float g_vs[P*L*D];
__device__ float g_ST[P*NC*C*C];   // g_ST[j*64+l] = S[l][j]
__device__ float g_ksum[P*NC*D];
__device__ float g_qsum[P*NC*D];
__device__ float g_kso[P*NC*D];
__device__ float g_qsi[P*NC*D];
__device__ float g_si[P*L];
__device__ float g_so[P*L];
__device__ float g_rk[P*L];
__device__ float g_rq[P*L];
__device__ float g_sa[P*L];
__device__ float g_es[P*L];
__device__ float g_essum[P*NC];
__device__ float g_kvc[P*NC*D*D];

typedef unsigned long long ull;
__device__ __forceinline__ ull pack2(float a, float b){
  ull r; asm("mov.b64 %0, {%1,%2};" : "=l"(r) : "f"(a), "f"(b)); return r;
}
__device__ __forceinline__ void fma2(ull &acc, ull a, ull b){
  asm("fma.rn.f32x2 %0, %1, %2, %0;" : "+l"(acc) : "l"(a), "l"(b));
}
__device__ __forceinline__ ull mul2(ull a, ull b){
  ull r; asm("mul.rn.f32x2 %0, %1, %2;" : "=l"(r) : "l"(a), "l"(b)); return r;
}
__device__ __forceinline__ float2 unpack2(ull v){
  float2 r; asm("mov.b64 {%0,%1}, %2;" : "=f"(r.x), "=f"(r.y) : "l"(v)); return r;
}
__device__ __forceinline__ float sigmoidf_(float x){ return 1.f/(1.f+__expf(-x)); }
__device__ __forceinline__ float f4get(const float4& v, int u){
  return (u==0)?v.x:(u==1)?v.y:(u==2)?v.z:v.w;
}

// ---------------- K1: sigmoid + chunk sums (256 thr) ----------------
__global__ void __launch_bounds__(256) k_prep(const float* __restrict__ Q, const float* __restrict__ K){
  __shared__ float2 ps[256];
  int c = blockIdx.x, p = blockIdx.y;
  int t = threadIdx.x, d = t&63, g = t>>6;
  const float* Qp = Q + (size_t)(p>>3)*LHD + (size_t)(p&7)*D + d;
  const float* Kp = K + (size_t)(p>>3)*LHD + (size_t)(p&7)*D + d;
  int l0 = c*C;
  int ob = (p*L + l0)*D + d;
  float ks=0.f, qs=0.f;
  #pragma unroll 4
  for(int j=g; j<C; j+=4){
    float qv = sigmoidf_(Qp[(size_t)(l0+j)*HD]);
    float kv = sigmoidf_(Kp[(size_t)(l0+j)*HD]);
    g_sq[ob + j*D] = qv;
    g_sk[ob + j*D] = kv;
    qs += qv; ks += kv;
  }
  ps[t] = make_float2(ks, qs);
  __syncthreads();
  if(t < 64){
    float2 a=ps[t], b=ps[t+64], cc=ps[t+128], dd=ps[t+192];
    g_ksum[(p*NC+c)*D+t] = a.x+b.x+cc.x+dd.x;
    g_qsum[(p*NC+c)*D+t] = a.y+b.y+cc.y+dd.y;
  }
}

// ---------------- K2: gram + si/so (256 thr, 4x4 reg tiles) ----------------
__global__ void __launch_bounds__(256) k_siso(){
  extern __shared__ float sm[];
  float* sqs = sm;               // [l][d] stride 64 (broadcast-only row reads + col reads)
  float* skT = sm + C*D;         // [d][j] stride SDT
  float* Ssm = sm + C*D + C*SDT; // [l][j] stride SDS
  __shared__ float rsk[C], rsq[C], kpre[D], qpre[D], b1s[C], b2s[C], sis[C], sos[C];
  int c=blockIdx.x, p=blockIdx.y, t=threadIdx.x;
  int base = (p*L + c*C)*D;
  const float4* gq = (const float4*)(g_sq+base);
  const float4* gk = (const float4*)(g_sk+base);
  #pragma unroll
  for(int i=t;i<1024;i+=256){
    int row = i>>4, col4 = (i&15)*4;
    *(float4*)(sqs + row*D + col4) = gq[i];
    float4 k4 = gk[i];
    skT[(col4  )*SDT + row] = k4.x;
    skT[(col4+1)*SDT + row] = k4.y;
    skT[(col4+2)*SDT + row] = k4.z;
    skT[(col4+3)*SDT + row] = k4.w;
  }
  if(t<64){
    float a=0.f; for(int cp=0;cp<c;cp++) a += g_ksum[(p*NC+cp)*D+t];
    kpre[t]=a;
  } else if(t<128){
    int d=t-64; float a=0.f; for(int cp=0;cp<c;cp++) a += g_qsum[(p*NC+cp)*D+d];
    qpre[d]=a;
  }
  __syncthreads();

  // scalar per-l dots
  if(t<64){
    int l=t; float rq=0.f, b1=0.f;
    for(int dd=0;dd<D;dd+=4){
      float4 q4 = *(const float4*)(sqs + l*D + dd);
      rq += q4.x+q4.y+q4.z+q4.w;
      b1 += (q4.x+EPSF)*(kpre[dd]+EPSF) + (q4.y+EPSF)*(kpre[dd+1]+EPSF)
          + (q4.z+EPSF)*(kpre[dd+2]+EPSF) + (q4.w+EPSF)*(kpre[dd+3]+EPSF);
    }
    rsq[l]=rq; b1s[l]=b1;
  } else if(t<128){
    int l=t-64; float rk=0.f, b2=0.f;
    for(int d=0;d<D;d++){
      float kv = skT[d*SDT + l];
      rk += kv; b2 += (kv+EPSF)*(qpre[d]+EPSF);
    }
    rsk[l]=rk; b2s[l]=b2;
  }

  // gram: 4l x 4j per thread
  int l0 = 4*(t>>4), j0 = 4*(t&15);
  ull acc[8];
  #pragma unroll
  for(int m=0;m<8;m++) acc[m]=0ull;
  #pragma unroll 4
  for(int dq=0; dq<D; dq+=4){
    float4 q4[4];
    #pragma unroll
    for(int ll=0;ll<4;ll++) q4[ll] = *(const float4*)(sqs + (l0+ll)*D + dq);
    #pragma unroll
    for(int du=0;du<4;du++){
      double2 ka = *(const double2*)(skT + (dq+du)*SDT + j0);
      ull k0=(ull)__double_as_longlong(ka.x), k1=(ull)__double_as_longlong(ka.y);
      #pragma unroll
      for(int ll=0;ll<4;ll++){
        float qv = f4get(q4[ll], du);
        ull q2 = pack2(qv,qv);
        fma2(acc[ll*2],   q2, k0);
        fma2(acc[ll*2+1], q2, k1);
      }
    }
  }
  float vals[4][4];
  #pragma unroll
  for(int ll=0;ll<4;ll++){
    float2 a0=unpack2(acc[ll*2]), a1=unpack2(acc[ll*2+1]);
    vals[ll][0]=a0.x; vals[ll][1]=a0.y; vals[ll][2]=a1.x; vals[ll][3]=a1.y;
    *(float4*)(Ssm + (l0+ll)*SDS + j0) = make_float4(a0.x,a0.y,a1.x,a1.y);
  }
  // direct register -> g_ST store (g_ST[j*64+l] = S[l][j])
  int stbase = (p*NC+c)*C*C;
  #pragma unroll
  for(int jj=0;jj<4;jj++)
    *(float4*)(g_ST + stbase + (j0+jj)*C + l0) =
      make_float4(vals[0][jj], vals[1][jj], vals[2][jj], vals[3][jj]);
  __syncthreads();

  // causal sums
  if(t<64){
    int l=t; float dot1=b1s[l];
    for(int i=0;i<=l;i++) dot1 += Ssm[l*SDS+i] + EPSF*rsk[i];
    float nrm = (float)(c*C + l + 1);
    float si = nrm/dot1;
    sis[l]=si;
    int gl = p*L + c*C + l;
    g_si[gl]=si; g_rq[gl]=rsq[l];
  } else if(t<128){
    int l=t-64; float dot2=b2s[l];
    for(int i=0;i<=l;i++) dot2 += Ssm[i*SDS+l] + EPSF*rsq[i];
    float nrm = (float)(c*C + l + 1);
    float so = nrm/dot2;
    sos[l]=so;
    int gl = p*L + c*C + l;
    g_so[gl]=so; g_rk[gl]=rsk[l];
  }
  __syncthreads();

  if(t<64){
    int d=t; float a1=0.f;
    for(int j=0;j<C;j++) a1 += skT[d*SDT+j]*sos[j];
    g_kso[(p*NC+c)*D+d] = a1;
  } else if(t<128){
    int d=t-64; float a2=0.f;
    for(int j=0;j<C;j++) a2 += sqs[j*D+d]*sis[j];
    g_qsi[(p*NC+c)*D+d] = a2;
  }
}

// ---------------- K3: conserved (256 thr) ----------------
__global__ void __launch_bounds__(256) k_conserved(){
  extern __shared__ float sm[];
  float* sqs = sm;               // [l][d] stride 64
  float* sks = sm + C*D;         // [l][d] stride 64
  float* STs = sm + 2*C*D;       // [j][l] stride SDS
  __shared__ float rskv[C], rsqv[C], sis[C], sos[C], kpre[D], qpre[D], facs[C], essh[C];
  int c=blockIdx.x, p=blockIdx.y, t=threadIdx.x;
  int base = (p*L + c*C)*D;
  int stbase = (p*NC+c)*C*C;
  const float4* gq = (const float4*)(g_sq+base);
  const float4* gk = (const float4*)(g_sk+base);
  const float4* gs = (const float4*)(g_ST+stbase);
  #pragma unroll
  for(int i=t;i<1024;i+=256){
    int row = i>>4, col4 = (i&15)*4;
    *(float4*)(sqs + row*D + col4) = gq[i];
    *(float4*)(sks + row*D + col4) = gk[i];
    *(float4*)(STs + row*SDS + col4) = gs[i];
  }
  if(t<64){
    int gl = p*L + c*C + t;
    rskv[t]=g_rk[gl]; sos[t]=g_so[gl];
    float a=0.f; for(int cp=0;cp<c;cp++) a += g_kso[(p*NC+cp)*D+t];
    kpre[t]=a;
  } else if(t<128){
    int l=t-64; int gl = p*L + c*C + l;
    rsqv[l]=g_rq[gl]; sis[l]=g_si[gl];
    float a=0.f; for(int cp=0;cp<c;cp++) a += g_qsi[(p*NC+cp)*D+l];
    qpre[l]=a;
  }
  __syncthreads();

  if(t<64){
    int l=t; float b3=0.f;
    for(int dd=0;dd<D;dd+=4){
      float4 q4 = *(const float4*)(sqs + l*D + dd);
      b3 += (q4.x+EPSF)*(kpre[dd]+EPSF) + (q4.y+EPSF)*(kpre[dd+1]+EPSF)
          + (q4.z+EPSF)*(kpre[dd+2]+EPSF) + (q4.w+EPSF)*(kpre[dd+3]+EPSF);
    }
    for(int i=0;i<=l;i++) b3 += sos[i]*(STs[i*SDS+l] + EPSF*rskv[i]);
    float nrm = (float)(c*C + l + 1);
    float sa = sigmoidf_(b3/nrm);
    g_sa[p*L + c*C + l] = sa;
  } else if(t<128){
    int l=t-64; float b4=0.f;
    for(int dd=0;dd<D;dd+=4){
      float4 k4 = *(const float4*)(sks + l*D + dd);
      b4 += (k4.x+EPSF)*(qpre[dd]+EPSF) + (k4.y+EPSF)*(qpre[dd+1]+EPSF)
          + (k4.z+EPSF)*(qpre[dd+2]+EPSF) + (k4.w+EPSF)*(qpre[dd+3]+EPSF);
    }
    for(int i=0;i<=l;i++) b4 += sis[i]*(STs[l*SDS+i] + EPSF*rsqv[i]);
    float nrm = (float)(c*C + l + 1);
    float cso = b4/nrm; cso = fminf(1.f, fmaxf(-1.f, cso));
    float es = __expf(cso);
    g_es[p*L + c*C + l] = es;
    essh[l]=es;
    facs[l]=sis[l]/nrm;
  }
  __syncthreads();
  float4* gqo = (float4*)(g_sq+base);
  #pragma unroll
  for(int i=t;i<1024;i+=256){
    int row = i>>4, col4 = (i&15)*4;
    float4 v = *(const float4*)(sqs + row*D + col4);
    float f = facs[row];
    gqo[i] = make_float4(v.x*f, v.y*f, v.z*f, v.w*f);
  }
  if(t<32){
    float v = essh[t] + essh[t+32];
    #pragma unroll
    for(int o=16;o;o>>=1) v += __shfl_down_sync(0xffffffffu, v, o);
    if(t==0) g_essum[p*NC+c] = v;
  }
}

// ---------------- K4: v_scaled + chunk KV (256 thr, 4x4 tiles) ----------------
__global__ void __launch_bounds__(256) k_vkv(const float* __restrict__ V){
  __shared__ __align__(16) float sks[C*D];
  __shared__ __align__(16) float vss[C*D];
  __shared__ float ess[C], comp[C];
  __shared__ float prefsh, wtot0;
  int c=blockIdx.x, p=blockIdx.y, t=threadIdx.x;
  int base = (p*L + c*C)*D;
  const float4* gk = (const float4*)(g_sk+base);
  #pragma unroll
  for(int i=t;i<1024;i+=256) ((float4*)sks)[i] = gk[i];
  if(t<64) ess[t] = g_es[p*L + c*C + t];
  if(t<32){
    float v = (t < c) ? g_essum[p*NC + t] : 0.f;
    #pragma unroll
    for(int o=16;o;o>>=1) v += __shfl_down_sync(0xffffffffu, v, o);
    if(t==0) prefsh = v;
  }
  __syncthreads();
  float xscan = 0.f;
  if(t<64){
    xscan = ess[t];
    #pragma unroll
    for(int o=1;o<32;o<<=1){
      float y = __shfl_up_sync(0xffffffffu, xscan, o);
      if((t&31) >= o) xscan += y;
    }
    if(t==31) wtot0 = xscan;
  }
  __syncthreads();
  if(t<64){
    float cum = prefsh + xscan + ((t>=32)? wtot0 : 0.f);
    comp[t] = ess[t]/cum * (float)(c*C + t + 1);
  }
  __syncthreads();
  const float* Vp = V + (size_t)(p>>3)*LHD + (size_t)(p&7)*D;
  float4* gvs = (float4*)(g_vs+base);
  #pragma unroll
  for(int i=t;i<1024;i+=256){
    int j = i>>4, col4 = (i&15)*4;
    float4 v = *(const float4*)(Vp + (size_t)(c*C+j)*HD + col4);
    float f = comp[j];
    float4 x = make_float4(v.x*f, v.y*f, v.z*f, v.w*f);
    ((float4*)vss)[i] = x;
    gvs[i] = x;
  }
  __syncthreads();
  // KV[d][m] += sk[j][d]*vs[j][m], tile 4d x 4m
  int d0 = 4*(t>>4), m0 = 4*(t&15);
  ull acc[8];
  #pragma unroll
  for(int m=0;m<8;m++) acc[m]=0ull;
  #pragma unroll 8
  for(int j=0;j<C;j++){
    float4 sk4 = *(const float4*)(sks + j*D + d0);
    double2 va = *(const double2*)(vss + j*D + m0);
    ull v0=(ull)__double_as_longlong(va.x), v1=(ull)__double_as_longlong(va.y);
    #pragma unroll
    for(int dd=0;dd<4;dd++){
      float a = f4get(sk4, dd);
      ull a2 = pack2(a,a);
      fma2(acc[dd*2],   a2, v0);
      fma2(acc[dd*2+1], a2, v1);
    }
  }
  size_t kb = (size_t)(p*NC+c)*D*D;
  #pragma unroll
  for(int dd=0;dd<4;dd++){
    float2 u0=unpack2(acc[dd*2]), u1=unpack2(acc[dd*2+1]);
    *(float4*)(g_kvc + kb + (d0+dd)*D + m0) = make_float4(u0.x,u0.y,u1.x,u1.y);
  }
}

// ---------------- K5: exclusive scan of chunk KV sums ----------------
__global__ void k_scan_kv(){
  int p = blockIdx.y;
  int e4 = blockIdx.x*256 + threadIdx.x;
  size_t stride = (size_t)D*D;
  size_t base = (size_t)p*NC*stride + (size_t)e4*4;
  float4 run = make_float4(0.f,0.f,0.f,0.f);
  #pragma unroll
  for(int c=0;c<NC;c++){
    float4 v = *(const float4*)(g_kvc + base + c*stride);
    *(float4*)(g_kvc + base + c*stride) = run;
    run.x += v.x; run.y += v.y; run.z += v.z; run.w += v.w;
  }
}

// ---------------- K6: causal output (256 thr, 4x4 tiles) ----------------
__global__ void __launch_bounds__(256) k_out(float* __restrict__ OUT){
  extern __shared__ float sm[];
  float* qss = sm;             // [l][d] stride 64 (broadcast-only)
  float* STs = sm + C*D;       // [i][l] stride 64 (S[l][i] at STs[i*64+l]; broadcast-only)
  float* vss = sm + 2*C*D;     // [i][m] stride 64
  float* kvs = sm + 3*C*D;     // [d][m] stride 64
  __shared__ float sa_s[C], fls[C];
  int c=blockIdx.x, p=blockIdx.y, t=threadIdx.x;
  int base = (p*L + c*C)*D;
  size_t kb = (size_t)(p*NC+c)*D*D;
  int stbase = (p*NC+c)*C*C;
  const float4* gq = (const float4*)(g_sq+base);
  const float4* gs = (const float4*)(g_ST+stbase);
  const float4* gv = (const float4*)(g_vs+base);
  const float4* gkv = (const float4*)(g_kvc+kb);
  #pragma unroll
  for(int i=t;i<1024;i+=256){
    ((float4*)qss)[i] = gq[i];
    ((float4*)STs)[i] = gs[i];
    ((float4*)vss)[i] = gv[i];
    ((float4*)kvs)[i] = gkv[i];
  }
  if(t<64){
    int gl = p*L + c*C + t;
    sa_s[t] = g_sa[gl];
    fls[t]  = g_si[gl] / (float)(c*C + t + 1);
  }
  __syncthreads();

  int l0 = 4*(t>>4), m0 = 4*(t&15);
  ull acc[8];
  #pragma unroll
  for(int m=0;m<8;m++) acc[m]=0ull;

  // intra-chunk: acc[ll][m] += S[l][i]*vs[i][m], i <= l
  #pragma unroll 4
  for(int i=0;i<=l0+3;i++){
    float4 st4 = *(const float4*)(STs + i*D + l0);
    double2 va = *(const double2*)(vss + i*D + m0);
    ull v0=(ull)__double_as_longlong(va.x), v1=(ull)__double_as_longlong(va.y);
    #pragma unroll
    for(int ll=0;ll<4;ll++){
      float s = (i <= l0+ll) ? f4get(st4, ll) : 0.f;
      ull s2 = pack2(s,s);
      fma2(acc[ll*2],   s2, v0);
      fma2(acc[ll*2+1], s2, v1);
    }
  }
  // scale intra by fl
  #pragma unroll
  for(int ll=0;ll<4;ll++){
    float f = fls[l0+ll];
    ull f2 = pack2(f,f);
    acc[ll*2]   = mul2(acc[ll*2],   f2);
    acc[ll*2+1] = mul2(acc[ll*2+1], f2);
  }
  // inter-chunk: acc[ll][m] += q_scaled[l][d]*KV[d][m]
  #pragma unroll 4
  for(int dq=0; dq<D; dq+=4){
    float4 q4[4];
    #pragma unroll
    for(int ll=0;ll<4;ll++) q4[ll] = *(const float4*)(qss + (l0+ll)*D + dq);
    #pragma unroll
    for(int du=0;du<4;du++){
      double2 ka = *(const double2*)(kvs + (dq+du)*D + m0);
      ull k0=(ull)__double_as_longlong(ka.x), k1=(ull)__double_as_longlong(ka.y);
      #pragma unroll
      for(int ll=0;ll<4;ll++){
        float qv = f4get(q4[ll], du);
        ull q2 = pack2(qv,qv);
        fma2(acc[ll*2],   q2, k0);
        fma2(acc[ll*2+1], q2, k1);
      }
    }
  }
  float* op = OUT + (size_t)(p>>3)*LHD + (size_t)(c*C)*HD + (size_t)(p&7)*D;
  #pragma unroll
  for(int ll=0;ll<4;ll++){
    float sa = sa_s[l0+ll];
    float2 a0=unpack2(acc[ll*2]), a1=unpack2(acc[ll*2+1]);
    *(float4*)(op + (size_t)(l0+ll)*HD + m0) =
      make_float4(a0.x*sa, a0.y*sa, a1.x*sa, a1.y*sa);
  }
}

// ---------------- launch ----------------
extern "C" void kernel_launch(void* const* d_in, const int* in_sizes, int n_in,
                              void* d_out, int out_size){
  const float* Q = (const float*)d_in[0];
  const float* K = (const float*)d_in[1];
  const float* V = (const float*)d_in[2];
  float* OUT = (float*)d_out;

  const int SM_SISO = (C*D + C*SDT + C*SDS)*sizeof(float);  // 51200
  const int SM_CONS = (2*C*D + C*SDS)*sizeof(float);        // 50176
  const int SM_OUT  = (4*C*D)*sizeof(float);                // 65536
  cudaFuncSetAttribute(k_siso,      cudaFuncAttributeMaxDynamicSharedMemorySize, SM_SISO);
  cudaFuncSetAttribute(k_conserved, cudaFuncAttributeMaxDynamicSharedMemorySize, SM_CONS);
  cudaFuncSetAttribute(k_out,       cudaFuncAttributeMaxDynamicSharedMemorySize, SM_OUT);

  dim3 gpc(NC, P);
  k_prep<<<gpc, 256>>>(Q, K);
  k_siso<<<gpc, 256, SM_SISO>>>();
  k_conserved<<<gpc, 256, SM_CONS>>>();
  k_vkv<<<gpc, 256>>>(V);
  k_scan_kv<<<dim3(4, P), 256>>>();
  k_out<<<gpc, 256, SM_OUT>>>(OUT);
}

// round 9
// speedup vs baseline: 2.1220x; 1.0453x over previous
#include <cuda_runtime.h>
#include <math.h>
#include <stdint.h>

#define NB   2
#define L    2048
#define H    8
#define D    64
#define HD   512
#define LHD  1048576
#define P    16
#define C    64
#define NC   32
#define EPSF 1e-6f
#define SDT  68      // padded stride (floats), 16B-aligned rows

// ---------------- scratch ----------------
__device__ float g_sq[P*L*D];      // sigmoid(q); overwritten with q_scaled
__device__ float g_sk[P*L*D];
__device__ float g_ST[P*NC*C*C];   // g_ST[j*64+l] = S[l][j]
__device__ float g_ksum[P*NC*D];
__device__ float g_qsum[P*NC*D];
__device__ float g_kso[P*NC*D];
__device__ float g_qsi[P*NC*D];
__device__ float g_si[P*L];
__device__ float g_so[P*L];
__device__ float g_rk[P*L];
__device__ float g_rq[P*L];
__device__ float g_sa[P*L];
__device__ float g_es[P*L];
__device__ float g_comp[P*L];      // source_competition factor
__device__ float g_essum[P*NC];
__device__ float g_kvc[P*NC*D*D];

typedef unsigned long long ull;
__device__ __forceinline__ ull pack2(float a, float b){
  ull r; asm("mov.b64 %0, {%1,%2};" : "=l"(r) : "f"(a), "f"(b)); return r;
}
__device__ __forceinline__ void fma2(ull &acc, ull a, ull b){
  asm("fma.rn.f32x2 %0, %1, %2, %0;" : "+l"(acc) : "l"(a), "l"(b));
}
__device__ __forceinline__ ull mul2(ull a, ull b){
  ull r; asm("mul.rn.f32x2 %0, %1, %2;" : "=l"(r) : "l"(a), "l"(b)); return r;
}
__device__ __forceinline__ float2 unpack2(ull v){
  float2 r; asm("mov.b64 {%0,%1}, %2;" : "=f"(r.x), "=f"(r.y) : "l"(v)); return r;
}
__device__ __forceinline__ float sigmoidf_(float x){ return 1.f/(1.f+__expf(-x)); }
__device__ __forceinline__ float f4get(const float4& v, int u){
  return (u==0)?v.x:(u==1)?v.y:(u==2)?v.z:v.w;
}
__device__ __forceinline__ float red4(float v){
  v += __shfl_xor_sync(0xffffffffu, v, 1);
  v += __shfl_xor_sync(0xffffffffu, v, 2);
  return v;
}

// ---------------- K1: sigmoid + chunk sums (256 thr) ----------------
__global__ void __launch_bounds__(256) k_prep(const float* __restrict__ Q, const float* __restrict__ K){
  __shared__ float2 ps[256];
  int c = blockIdx.x, p = blockIdx.y;
  int t = threadIdx.x, d = t&63, g = t>>6;
  const float* Qp = Q + (size_t)(p>>3)*LHD + (size_t)(p&7)*D + d;
  const float* Kp = K + (size_t)(p>>3)*LHD + (size_t)(p&7)*D + d;
  int l0 = c*C;
  int ob = (p*L + l0)*D + d;
  float ks=0.f, qs=0.f;
  #pragma unroll 4
  for(int j=g; j<C; j+=4){
    float qv = sigmoidf_(Qp[(size_t)(l0+j)*HD]);
    float kv = sigmoidf_(Kp[(size_t)(l0+j)*HD]);
    g_sq[ob + j*D] = qv;
    g_sk[ob + j*D] = kv;
    qs += qv; ks += kv;
  }
  ps[t] = make_float2(ks, qs);
  __syncthreads();
  if(t < 64){
    float2 a=ps[t], b=ps[t+64], cc=ps[t+128], dd=ps[t+192];
    g_ksum[(p*NC+c)*D+t] = a.x+b.x+cc.x+dd.x;
    g_qsum[(p*NC+c)*D+t] = a.y+b.y+cc.y+dd.y;
  }
}

// ---------------- K2: gram + si/so (256 thr, 4x4 tiles, 4-way scalar split) ----------------
__global__ void __launch_bounds__(256) k_siso(){
  extern __shared__ float sm[];
  float* sqs = sm;                 // [l][d] stride 68
  float* skT = sm + C*SDT;         // [d][j] stride 68
  float* Ssm = sm + 2*C*SDT;       // [l][j] stride 68
  __shared__ float rsk[C], rsq[C], b1s[C], b2s[C], sis[C], sos[C], kpre[D], qpre[D];
  __shared__ float2 ps2[256];
  int c=blockIdx.x, p=blockIdx.y, t=threadIdx.x;
  int base = (p*L + c*C)*D;
  const float4* gq = (const float4*)(g_sq+base);
  const float4* gk = (const float4*)(g_sk+base);
  #pragma unroll
  for(int i=t;i<1024;i+=256){
    int row = i>>4, col4 = (i&15)*4;
    *(float4*)(sqs + row*SDT + col4) = gq[i];
    float4 k4 = gk[i];
    skT[(col4  )*SDT + row] = k4.x;
    skT[(col4+1)*SDT + row] = k4.y;
    skT[(col4+2)*SDT + row] = k4.z;
    skT[(col4+3)*SDT + row] = k4.w;
  }
  { int d=t&63, g=t>>6; float a=0.f, b=0.f;
    for(int cp=g;cp<c;cp+=4){ a += g_ksum[(p*NC+cp)*D+d]; b += g_qsum[(p*NC+cp)*D+d]; }
    ps2[t] = make_float2(a,b);
  }
  __syncthreads();
  if(t<64){
    kpre[t] = ps2[t].x+ps2[t+64].x+ps2[t+128].x+ps2[t+192].x;
    qpre[t] = ps2[t].y+ps2[t+64].y+ps2[t+128].y+ps2[t+192].y;
  }
  __syncthreads();

  int ls = t>>2, gs = t&3;
  // Section A: per-l dots, 4-way split
  { float rq=0.f, b1=0.f, rk=0.f, b2=0.f;
    #pragma unroll
    for(int u=0;u<4;u++){
      int dd = 16*gs + 4*u;
      float4 q4 = *(const float4*)(sqs + ls*SDT + dd);
      rq += q4.x+q4.y+q4.z+q4.w;
      b1 += (q4.x+EPSF)*(kpre[dd]+EPSF) + (q4.y+EPSF)*(kpre[dd+1]+EPSF)
          + (q4.z+EPSF)*(kpre[dd+2]+EPSF) + (q4.w+EPSF)*(kpre[dd+3]+EPSF);
    }
    #pragma unroll
    for(int u=0;u<16;u++){
      int d = 4*u + gs;
      float kv = skT[d*SDT + ls];
      rk += kv; b2 += (kv+EPSF)*(qpre[d]+EPSF);
    }
    rq = red4(rq); b1 = red4(b1); rk = red4(rk); b2 = red4(b2);
    if(gs==0){ rsq[ls]=rq; b1s[ls]=b1; rsk[ls]=rk; b2s[ls]=b2; }
  }

  // gram: 4l x 4j per thread
  int l0 = 4*(t>>4), j0 = 4*(t&15);
  ull acc[8];
  #pragma unroll
  for(int m=0;m<8;m++) acc[m]=0ull;
  #pragma unroll 4
  for(int dq=0; dq<D; dq+=4){
    float4 q4[4];
    #pragma unroll
    for(int ll=0;ll<4;ll++) q4[ll] = *(const float4*)(sqs + (l0+ll)*SDT + dq);
    #pragma unroll
    for(int du=0;du<4;du++){
      double2 ka = *(const double2*)(skT + (dq+du)*SDT + j0);
      ull k0=(ull)__double_as_longlong(ka.x), k1=(ull)__double_as_longlong(ka.y);
      #pragma unroll
      for(int ll=0;ll<4;ll++){
        float qv = f4get(q4[ll], du);
        ull q2 = pack2(qv,qv);
        fma2(acc[ll*2],   q2, k0);
        fma2(acc[ll*2+1], q2, k1);
      }
    }
  }
  float vals[4][4];
  #pragma unroll
  for(int ll=0;ll<4;ll++){
    float2 a0=unpack2(acc[ll*2]), a1=unpack2(acc[ll*2+1]);
    vals[ll][0]=a0.x; vals[ll][1]=a0.y; vals[ll][2]=a1.x; vals[ll][3]=a1.y;
    *(float4*)(Ssm + (l0+ll)*SDT + j0) = make_float4(a0.x,a0.y,a1.x,a1.y);
  }
  int stbase = (p*NC+c)*C*C;
  #pragma unroll
  for(int jj=0;jj<4;jj++)
    *(float4*)(g_ST + stbase + (j0+jj)*C + l0) =
      make_float4(vals[0][jj], vals[1][jj], vals[2][jj], vals[3][jj]);
  __syncthreads();

  // Section B: causal sums, 4-way split
  { float d1=0.f, d2=0.f;
    for(int i=gs; i<=ls; i+=4){
      d1 += Ssm[ls*SDT+i] + EPSF*rsk[i];
      d2 += Ssm[i*SDT+ls] + EPSF*rsq[i];
    }
    d1 = red4(d1); d2 = red4(d2);
    if(gs==0){
      float dot1 = b1s[ls] + d1, dot2 = b2s[ls] + d2;
      float nrm = (float)(c*C + ls + 1);
      float si = nrm/dot1, so = nrm/dot2;
      sis[ls]=si; sos[ls]=so;
      int gl = p*L + c*C + ls;
      g_si[gl]=si; g_so[gl]=so; g_rk[gl]=rsk[ls]; g_rq[gl]=rsq[ls];
    }
  }
  __syncthreads();

  // Section C: kso/qsi chunk sums, 4-way split (thread = (d=ls, quarter gs))
  { float a1=0.f, a2=0.f;
    #pragma unroll
    for(int u=0;u<16;u++){
      int j = 4*u + gs;
      a1 += skT[ls*SDT+j]*sos[j];
      a2 += sqs[j*SDT+ls]*sis[j];
    }
    a1 = red4(a1); a2 = red4(a2);
    if(gs==0){
      g_kso[(p*NC+c)*D+ls] = a1;
      g_qsi[(p*NC+c)*D+ls] = a2;
    }
  }
}

// ---------------- K3: conserved (256 thr, 4-way split) ----------------
__global__ void __launch_bounds__(256) k_conserved(){
  extern __shared__ float sm[];
  float* sqs = sm;               // [l][d] stride 68
  float* sks = sm + C*SDT;       // [l][d] stride 68
  float* STs = sm + 2*C*SDT;     // [j][l] stride 68 (S[l][j] at STs[j*SDT+l])
  __shared__ float rskv[C], rsqv[C], sis[C], sos[C], kpre[D], qpre[D], facs[C], essh[C];
  __shared__ float2 ps2[256];
  int c=blockIdx.x, p=blockIdx.y, t=threadIdx.x;
  int base = (p*L + c*C)*D;
  int stbase = (p*NC+c)*C*C;
  const float4* gq = (const float4*)(g_sq+base);
  const float4* gk = (const float4*)(g_sk+base);
  const float4* gst = (const float4*)(g_ST+stbase);
  #pragma unroll
  for(int i=t;i<1024;i+=256){
    int row = i>>4, col4 = (i&15)*4;
    *(float4*)(sqs + row*SDT + col4) = gq[i];
    *(float4*)(sks + row*SDT + col4) = gk[i];
    *(float4*)(STs + row*SDT + col4) = gst[i];
  }
  { int d=t&63, g=t>>6; float a=0.f, b=0.f;
    for(int cp=g;cp<c;cp+=4){ a += g_kso[(p*NC+cp)*D+d]; b += g_qsi[(p*NC+cp)*D+d]; }
    ps2[t] = make_float2(a,b);
  }
  if(t<64){
    int gl = p*L + c*C + t;
    rskv[t]=g_rk[gl]; sos[t]=g_so[gl];
  } else if(t<128){
    int l=t-64; int gl = p*L + c*C + l;
    rsqv[l]=g_rq[gl]; sis[l]=g_si[gl];
  }
  __syncthreads();
  if(t<64){
    kpre[t] = ps2[t].x+ps2[t+64].x+ps2[t+128].x+ps2[t+192].x;
    qpre[t] = ps2[t].y+ps2[t+64].y+ps2[t+128].y+ps2[t+192].y;
  }
  __syncthreads();

  int ls = t>>2, gs = t&3;
  { float b3=0.f, b4=0.f;
    #pragma unroll
    for(int u=0;u<4;u++){
      int dd = 16*gs + 4*u;
      float4 q4 = *(const float4*)(sqs + ls*SDT + dd);
      float4 k4 = *(const float4*)(sks + ls*SDT + dd);
      b3 += (q4.x+EPSF)*(kpre[dd]+EPSF) + (q4.y+EPSF)*(kpre[dd+1]+EPSF)
          + (q4.z+EPSF)*(kpre[dd+2]+EPSF) + (q4.w+EPSF)*(kpre[dd+3]+EPSF);
      b4 += (k4.x+EPSF)*(qpre[dd]+EPSF) + (k4.y+EPSF)*(qpre[dd+1]+EPSF)
          + (k4.z+EPSF)*(qpre[dd+2]+EPSF) + (k4.w+EPSF)*(qpre[dd+3]+EPSF);
    }
    for(int i=gs; i<=ls; i+=4){
      b3 += sos[i]*(STs[i*SDT+ls] + EPSF*rskv[i]);
      b4 += sis[i]*(STs[ls*SDT+i] + EPSF*rsqv[i]);
    }
    b3 = red4(b3); b4 = red4(b4);
    if(gs==0){
      float nrm = (float)(c*C + ls + 1);
      float sa = sigmoidf_(b3/nrm);
      float cso = b4/nrm; cso = fminf(1.f, fmaxf(-1.f, cso));
      float es = __expf(cso);
      int gl = p*L + c*C + ls;
      g_sa[gl] = sa; g_es[gl] = es;
      essh[ls]=es;
      facs[ls]=sis[ls]/nrm;
    }
  }
  __syncthreads();
  float4* gqo = (float4*)(g_sq+base);
  #pragma unroll
  for(int i=t;i<1024;i+=256){
    int row = i>>4, col4 = (i&15)*4;
    float4 v = *(const float4*)(sqs + row*SDT + col4);
    float f = facs[row];
    gqo[i] = make_float4(v.x*f, v.y*f, v.z*f, v.w*f);
  }
  if(t<32){
    float v = essh[t] + essh[t+32];
    #pragma unroll
    for(int o=16;o;o>>=1) v += __shfl_down_sync(0xffffffffu, v, o);
    if(t==0) g_essum[p*NC+c] = v;
  }
}

// ---------------- K4: v_scaled + chunk KV (256 thr, 4x4 tiles) ----------------
__global__ void __launch_bounds__(256) k_vkv(const float* __restrict__ V){
  __shared__ __align__(16) float sks[C*D];
  __shared__ __align__(16) float vss[C*D];
  __shared__ float ess[C], comp[C];
  __shared__ float prefsh, wtot0;
  int c=blockIdx.x, p=blockIdx.y, t=threadIdx.x;
  int base = (p*L + c*C)*D;
  const float4* gk = (const float4*)(g_sk+base);
  #pragma unroll
  for(int i=t;i<1024;i+=256) ((float4*)sks)[i] = gk[i];
  if(t<64) ess[t] = g_es[p*L + c*C + t];
  if(t<32){
    float v = (t < c) ? g_essum[p*NC + t] : 0.f;
    #pragma unroll
    for(int o=16;o;o>>=1) v += __shfl_down_sync(0xffffffffu, v, o);
    if(t==0) prefsh = v;
  }
  __syncthreads();
  float xscan = 0.f;
  if(t<64){
    xscan = ess[t];
    #pragma unroll
    for(int o=1;o<32;o<<=1){
      float y = __shfl_up_sync(0xffffffffu, xscan, o);
      if((t&31) >= o) xscan += y;
    }
    if(t==31) wtot0 = xscan;
  }
  __syncthreads();
  if(t<64){
    float cum = prefsh + xscan + ((t>=32)? wtot0 : 0.f);
    float cm = ess[t]/cum * (float)(c*C + t + 1);
    comp[t] = cm;
    g_comp[p*L + c*C + t] = cm;
  }
  __syncthreads();
  const float* Vp = V + (size_t)(p>>3)*LHD + (size_t)(p&7)*D;
  #pragma unroll
  for(int i=t;i<1024;i+=256){
    int j = i>>4, col4 = (i&15)*4;
    float4 v = *(const float4*)(Vp + (size_t)(c*C+j)*HD + col4);
    float f = comp[j];
    ((float4*)vss)[i] = make_float4(v.x*f, v.y*f, v.z*f, v.w*f);
  }
  __syncthreads();
  // KV[d][m] += sk[j][d]*vs[j][m], tile 4d x 4m
  int d0 = 4*(t>>4), m0 = 4*(t&15);
  ull acc[8];
  #pragma unroll
  for(int m=0;m<8;m++) acc[m]=0ull;
  #pragma unroll 8
  for(int j=0;j<C;j++){
    float4 sk4 = *(const float4*)(sks + j*D + d0);
    double2 va = *(const double2*)(vss + j*D + m0);
    ull v0=(ull)__double_as_longlong(va.x), v1=(ull)__double_as_longlong(va.y);
    #pragma unroll
    for(int dd=0;dd<4;dd++){
      float a = f4get(sk4, dd);
      ull a2 = pack2(a,a);
      fma2(acc[dd*2],   a2, v0);
      fma2(acc[dd*2+1], a2, v1);
    }
  }
  size_t kb = (size_t)(p*NC+c)*D*D;
  #pragma unroll
  for(int dd=0;dd<4;dd++){
    float2 u0=unpack2(acc[dd*2]), u1=unpack2(acc[dd*2+1]);
    *(float4*)(g_kvc + kb + (d0+dd)*D + m0) = make_float4(u0.x,u0.y,u1.x,u1.y);
  }
}

// ---------------- K5: exclusive scan of chunk KV sums ----------------
__global__ void k_scan_kv(){
  int p = blockIdx.y;
  int e4 = blockIdx.x*256 + threadIdx.x;
  size_t stride = (size_t)D*D;
  size_t base = (size_t)p*NC*stride + (size_t)e4*4;
  float4 run = make_float4(0.f,0.f,0.f,0.f);
  #pragma unroll
  for(int c=0;c<NC;c++){
    float4 v = *(const float4*)(g_kvc + base + c*stride);
    *(float4*)(g_kvc + base + c*stride) = run;
    run.x += v.x; run.y += v.y; run.z += v.z; run.w += v.w;
  }
}

// ---------------- K6: causal output (256 thr, 4x4 tiles) ----------------
__global__ void __launch_bounds__(256) k_out(float* __restrict__ OUT, const float* __restrict__ V){
  extern __shared__ float sm[];
  float* qss = sm;             // [l][d] stride 64 (broadcast-only)
  float* STs = sm + C*D;       // [i][l] stride 64 (S[l][i] at STs[i*64+l]; broadcast-only)
  float* vss = sm + 2*C*D;     // [i][m] stride 64
  float* kvs = sm + 3*C*D;     // [d][m] stride 64
  __shared__ float sa_s[C], fls[C];
  int c=blockIdx.x, p=blockIdx.y, t=threadIdx.x;
  int base = (p*L + c*C)*D;
  size_t kb = (size_t)(p*NC+c)*D*D;
  int stbase = (p*NC+c)*C*C;
  const float4* gq = (const float4*)(g_sq+base);
  const float4* gst = (const float4*)(g_ST+stbase);
  const float4* gkv = (const float4*)(g_kvc+kb);
  const float* Vp = V + (size_t)(p>>3)*LHD + (size_t)(p&7)*D;
  #pragma unroll
  for(int i=t;i<1024;i+=256){
    ((float4*)qss)[i] = gq[i];
    ((float4*)STs)[i] = gst[i];
    ((float4*)kvs)[i] = gkv[i];
    int row = i>>4, col4 = (i&15)*4;
    float cm = g_comp[p*L + c*C + row];
    float4 v = *(const float4*)(Vp + (size_t)(c*C+row)*HD + col4);
    ((float4*)vss)[i] = make_float4(v.x*cm, v.y*cm, v.z*cm, v.w*cm);
  }
  if(t<64){
    int gl = p*L + c*C + t;
    sa_s[t] = g_sa[gl];
    fls[t]  = g_si[gl] / (float)(c*C + t + 1);
  }
  __syncthreads();

  int l0 = 4*(t>>4), m0 = 4*(t&15);
  ull acc[8];
  #pragma unroll
  for(int m=0;m<8;m++) acc[m]=0ull;

  // intra-chunk: acc[ll][m] += S[l][i]*vs[i][m], i <= l
  #pragma unroll 4
  for(int i=0;i<=l0+3;i++){
    float4 st4 = *(const float4*)(STs + i*D + l0);
    double2 va = *(const double2*)(vss + i*D + m0);
    ull v0=(ull)__double_as_longlong(va.x), v1=(ull)__double_as_longlong(va.y);
    #pragma unroll
    for(int ll=0;ll<4;ll++){
      float s = (i <= l0+ll) ? f4get(st4, ll) : 0.f;
      ull s2 = pack2(s,s);
      fma2(acc[ll*2],   s2, v0);
      fma2(acc[ll*2+1], s2, v1);
    }
  }
  #pragma unroll
  for(int ll=0;ll<4;ll++){
    float f = fls[l0+ll];
    ull f2 = pack2(f,f);
    acc[ll*2]   = mul2(acc[ll*2],   f2);
    acc[ll*2+1] = mul2(acc[ll*2+1], f2);
  }
  // inter-chunk: acc[ll][m] += q_scaled[l][d]*KV[d][m]
  #pragma unroll 4
  for(int dq=0; dq<D; dq+=4){
    float4 q4[4];
    #pragma unroll
    for(int ll=0;ll<4;ll++) q4[ll] = *(const float4*)(qss + (l0+ll)*D + dq);
    #pragma unroll
    for(int du=0;du<4;du++){
      double2 ka = *(const double2*)(kvs + (dq+du)*D + m0);
      ull k0=(ull)__double_as_longlong(ka.x), k1=(ull)__double_as_longlong(ka.y);
      #pragma unroll
      for(int ll=0;ll<4;ll++){
        float qv = f4get(q4[ll], du);
        ull q2 = pack2(qv,qv);
        fma2(acc[ll*2],   q2, k0);
        fma2(acc[ll*2+1], q2, k1);
      }
    }
  }
  float* op = OUT + (size_t)(p>>3)*LHD + (size_t)(c*C)*HD + (size_t)(p&7)*D;
  #pragma unroll
  for(int ll=0;ll<4;ll++){
    float sa = sa_s[l0+ll];
    float2 a0=unpack2(acc[ll*2]), a1=unpack2(acc[ll*2+1]);
    *(float4*)(op + (size_t)(l0+ll)*HD + m0) =
      make_float4(a0.x*sa, a0.y*sa, a1.x*sa, a1.y*sa);
  }
}

// ---------------- launch ----------------
extern "C" void kernel_launch(void* const* d_in, const int* in_sizes, int n_in,
                              void* d_out, int out_size){
  const float* Q = (const float*)d_in[0];
  const float* K = (const float*)d_in[1];
  const float* V = (const float*)d_in[2];
  float* OUT = (float*)d_out;

  const int SM_3T  = 3*C*SDT*sizeof(float);   // 52224
  const int SM_OUT = 4*C*D*sizeof(float);     // 65536
  cudaFuncSetAttribute(k_siso,      cudaFuncAttributeMaxDynamicSharedMemorySize, SM_3T);
  cudaFuncSetAttribute(k_conserved, cudaFuncAttributeMaxDynamicSharedMemorySize, SM_3T);
  cudaFuncSetAttribute(k_out,       cudaFuncAttributeMaxDynamicSharedMemorySize, SM_OUT);

  dim3 gpc(NC, P);
  k_prep<<<gpc, 256>>>(Q, K);
  k_siso<<<gpc, 256, SM_3T>>>();
  k_conserved<<<gpc, 256, SM_3T>>>();
  k_vkv<<<gpc, 256>>>(V);
  k_scan_kv<<<dim3(4, P), 256>>>();
  k_out<<<gpc, 256, SM_OUT>>>(OUT, V);
}